// round 12
// baseline (speedup 1.0000x reference)
#include <cuda_runtime.h>
#include <stdint.h>

// Problem constants (fixed by the reference)
#define SEQ_LEN   2048
#define NUM_HEADS 16
#define BATCH     2
#define RB_PITCH  4096   // floats per (h, m) reversed-bias copy

// Reversed bias, 4 pre-shifted copies per head:
//   rev[h][u] = bias(delta = 2047 - u):  u <= 2047 -> e1[2047-u, h]
//                                        u >= 2048 -> e2[u-2048, h]
//   g_rb[(h*4 + m)*RB_PITCH + x] = rev[h][x + m]   (m in 0..3)
// (Resubmission of R10 kernel after infra-only container failure.)
__device__ float g_rb[NUM_HEADS * 4 * RB_PITCH];

__global__ void build_bias_kernel(const float* __restrict__ e1,
                                  const float* __restrict__ e2) {
    int idx = blockIdx.x * blockDim.x + threadIdx.x;          // [0, 16*4*4096)
    const int total = NUM_HEADS * 4 * RB_PITCH;
    if (idx >= total) return;
    int x = idx & (RB_PITCH - 1);
    int hm = idx >> 12;           // h*4 + m
    int m = hm & 3;
    int h = hm >> 2;
    int u = x + m;                // reversed index
    float v = 0.0f;
    if (u <= 2 * SEQ_LEN - 2) {   // u in [0, 4094]
        if (u <= SEQ_LEN - 1) {
            v = e1[(SEQ_LEN - 1 - u) * NUM_HEADS + h];        // delta >= 0 side
        } else {
            v = e2[(u - SEQ_LEN) * NUM_HEADS + h];            // j > i side
        }
    }
    g_rb[idx] = v;
}

// TMA bulk-store writer.
// CTA = (h, m, q-block of 32). Stages copy (h,m) = 16KB in SMEM once, then
// each output row i = 2047 - 4q - m is the 8KB SMEM slice starting at byte
// 16*q (16B aligned). 32 rows x 2 batch planes = 64 cp.async.bulk stores.
#define Q_PER_CTA 32

__global__ __launch_bounds__(256)
void write_out_tma_kernel(char* __restrict__ out) {
    __shared__ __align__(16) float s_bias[RB_PITCH];   // 16KB

    unsigned bid = blockIdx.x;                 // [0, 16*4*16)
    unsigned qblk = bid & 15u;                 // 16 q-blocks of 32
    unsigned m = (bid >> 4) & 3u;
    unsigned h = bid >> 6;

    // Stage the (h,m) shifted copy into SMEM: 1024 float4, 256 threads x 4.
    const float4* __restrict__ src =
        reinterpret_cast<const float4*>(g_rb + (size_t)(h * 4u + m) * RB_PITCH);
    float4* dst4 = reinterpret_cast<float4*>(s_bias);
    unsigned t = threadIdx.x;
    #pragma unroll
    for (int k = 0; k < 4; k++)
        dst4[t + 256 * k] = src[t + 256 * k];
    __syncthreads();
    asm volatile("fence.proxy.async.shared::cta;" ::: "memory");

    if (threadIdx.x == 0) {
        uint32_t s_base;
        asm("{ .reg .u64 tmp; cvta.to.shared.u64 tmp, %1; cvt.u32.u64 %0, tmp; }"
            : "=r"(s_base) : "l"((const void*)s_bias));

        const size_t plane = (size_t)NUM_HEADS * SEQ_LEN * SEQ_LEN * sizeof(float); // 256MiB
        const size_t rowbytes = (size_t)SEQ_LEN * sizeof(float);                    // 8192

        #pragma unroll 4
        for (int r = 0; r < Q_PER_CTA; r++) {
            unsigned q = qblk * Q_PER_CTA + r;          // [0, 511]
            unsigned i = 2047u - 4u * q - m;            // row index
            uint32_t s_src = s_base + 16u * q;          // 16B aligned; slice [16q, 16q+8192) <= 16384. OK.
            char* g0 = out + ((size_t)h * SEQ_LEN + i) * rowbytes;
            char* g1 = g0 + plane;
            asm volatile(
                "cp.async.bulk.global.shared::cta.bulk_group [%0], [%1], %2;"
                :: "l"(g0), "r"(s_src), "r"((uint32_t)rowbytes) : "memory");
            asm volatile(
                "cp.async.bulk.global.shared::cta.bulk_group [%0], [%1], %2;"
                :: "l"(g1), "r"(s_src), "r"((uint32_t)rowbytes) : "memory");
        }
        asm volatile("cp.async.bulk.commit_group;" ::: "memory");
        asm volatile("cp.async.bulk.wait_group 0;" ::: "memory");
    }
    __syncthreads();
}

extern "C" void kernel_launch(void* const* d_in, const int* in_sizes, int n_in,
                              void* d_out, int out_size) {
    // metadata order: q (unused), e1, e2
    const float* e1 = (const float*)d_in[1];
    const float* e2 = (const float*)d_in[2];

    {
        const int total = NUM_HEADS * 4 * RB_PITCH;   // 262144
        int threads = 256;
        int blocks = total / threads;                 // 1024
        build_bias_kernel<<<blocks, threads>>>(e1, e2);
    }
    {
        // grid = H * 4 m-classes * 16 q-blocks = 1024 CTAs
        unsigned blocks = NUM_HEADS * 4 * (512 / Q_PER_CTA);
        write_out_tma_kernel<<<blocks, 256>>>((char*)d_out);
    }
}

// round 13
// speedup vs baseline: 1.1572x; 1.1572x over previous
#include <cuda_runtime.h>
#include <stdint.h>

// Problem constants (fixed by the reference)
#define SEQ_LEN   2048
#define NUM_HEADS 16
#define BATCH     2
#define RB_PITCH  4096   // floats per (h, m) reversed-bias copy

// Reversed bias, 4 pre-shifted copies per head for warp-uniform alignment:
//   rev[h][u] = bias(delta = 2047 - u):  u <= 2047 -> e1[2047-u, h]
//                                        u >= 2048 -> e2[u-2048, h]
//   g_rb[(h*4 + m)*RB_PITCH + x] = rev[h][x + m]   (m in 0..3)
// Total 1 MiB (L2-resident).
__device__ float g_rb[NUM_HEADS * 4 * RB_PITCH];

__global__ void build_bias_kernel(const float* __restrict__ e1,
                                  const float* __restrict__ e2) {
    int idx = blockIdx.x * blockDim.x + threadIdx.x;          // [0, 16*4*4096)
    const int total = NUM_HEADS * 4 * RB_PITCH;
    if (idx >= total) return;
    int x = idx & (RB_PITCH - 1);
    int hm = idx >> 12;           // h*4 + m
    int m = hm & 3;
    int h = hm >> 2;
    int u = x + m;                // reversed index
    float v = 0.0f;
    if (u <= 2 * SEQ_LEN - 2) {   // u in [0, 4094]
        if (u <= SEQ_LEN - 1) {
            v = e1[(SEQ_LEN - 1 - u) * NUM_HEADS + h];        // delta >= 0 side
        } else {
            v = e2[(u - SEQ_LEN) * NUM_HEADS + h];            // j > i side
        }
    }
    g_rb[idx] = v;
}

// Each thread: TWO independent aligned float4 reads (j4 and j4+256) and FOUR
// coalesced streaming float4 stores (both j-halves x both batch planes).
// All accesses keep 16B lane stride -> full 128B-line warp transactions.
__global__ __launch_bounds__(256)
void write_out_kernel(float4* __restrict__ out) {
    // tid layout: j4 fastest (256 = half row), then i (2048), then h (16)
    unsigned tid = blockIdx.x * blockDim.x + threadIdx.x;
    unsigned j4 = tid & 255u;            // covers j4 and j4+256
    unsigned rem = tid >> 8;
    unsigned i = rem & 2047u;
    unsigned h = rem >> 11;

    // d = 2047 - i = 4q + m (m warp-uniform)
    unsigned d = 2047u - i;
    unsigned q = d >> 2;
    unsigned m = d & 3u;

    // float index max: 4*(q + j4 + 256) + 3 <= 4*(511+511)+3 = 4091 < 4096. OK.
    const float4* __restrict__ p =
        reinterpret_cast<const float4*>(g_rb + (size_t)(h * 4u + m) * RB_PITCH) + q;
    float4 v0 = p[j4];            // bias(i, 4*j4 .. 4*j4+3)
    float4 v1 = p[j4 + 256u];     // bias(i, 4*(j4+256) .. +3)

    // out is float4-typed: 512 float4 per (h,i) row
    size_t row = (size_t)h * SEQ_LEN + i;                    // plane-row, batch 0
    size_t off0 = row * 512 + j4;
    size_t off1 = off0 + (size_t)NUM_HEADS * SEQ_LEN * 512;  // batch 1 plane

    __stcs(&out[off0],        v0);
    __stcs(&out[off0 + 256],  v1);
    __stcs(&out[off1],        v0);
    __stcs(&out[off1 + 256],  v1);
}

extern "C" void kernel_launch(void* const* d_in, const int* in_sizes, int n_in,
                              void* d_out, int out_size) {
    // metadata order: q (unused), e1, e2
    const float* e1 = (const float*)d_in[1];
    const float* e2 = (const float*)d_in[2];
    float4* out = (float4*)d_out;

    {
        const int total = NUM_HEADS * 4 * RB_PITCH;   // 262144
        int threads = 256;
        int blocks = total / threads;                 // 1024
        build_bias_kernel<<<blocks, threads>>>(e1, e2);
    }
    {
        // threads = H * S * (S/8) = 16 * 2048 * 256 = 8,388,608
        unsigned total = NUM_HEADS * SEQ_LEN * (SEQ_LEN / 8);
        int threads = 256;
        unsigned blocks = total / threads;            // 32768
        write_out_kernel<<<blocks, threads>>>(out);
    }
}

// round 14
// speedup vs baseline: 1.1756x; 1.0159x over previous
#include <cuda_runtime.h>
#include <stdint.h>

// Problem constants (fixed by the reference)
#define SEQ_LEN   2048
#define NUM_HEADS 16
#define BATCH     2
#define RB_PITCH  4096   // floats per (h, m) reversed-bias copy

// Reversed bias, 4 pre-shifted copies per head for warp-uniform alignment:
//   rev[h][u] = bias(delta = 2047 - u):  u <= 2047 -> e1[2047-u, h]
//                                        u >= 2048 -> e2[u-2048, h]
//   g_rb[(h*4 + m)*RB_PITCH + x] = rev[h][x + m]   (m in 0..3)
// Total 1 MiB (L2-resident).
__device__ float g_rb[NUM_HEADS * 4 * RB_PITCH];

__global__ void build_bias_kernel(const float* __restrict__ e1,
                                  const float* __restrict__ e2) {
    int idx = blockIdx.x * blockDim.x + threadIdx.x;          // [0, 16*4*4096)
    const int total = NUM_HEADS * 4 * RB_PITCH;
    if (idx >= total) return;
    int x = idx & (RB_PITCH - 1);
    int hm = idx >> 12;           // h*4 + m
    int m = hm & 3;
    int h = hm >> 2;
    int u = x + m;                // reversed index
    float v = 0.0f;
    if (u <= 2 * SEQ_LEN - 2) {   // u in [0, 4094]
        if (u <= SEQ_LEN - 1) {
            v = e1[(SEQ_LEN - 1 - u) * NUM_HEADS + h];        // delta >= 0 side
        } else {
            v = e2[(u - SEQ_LEN) * NUM_HEADS + h];            // j > i side
        }
    }
    g_rb[idx] = v;
}

// Each thread: TWO independent aligned float4 reads (j4 and j4+256) and FOUR
// coalesced streaming float4 stores (both j-halves x both batch planes).
// All accesses keep 16B lane stride -> full 128B-line warp transactions.
__global__ __launch_bounds__(256)
void write_out_kernel(float4* __restrict__ out) {
    // tid layout: j4 fastest (256 = half row), then i (2048), then h (16)
    unsigned tid = blockIdx.x * blockDim.x + threadIdx.x;
    unsigned j4 = tid & 255u;            // covers j4 and j4+256
    unsigned rem = tid >> 8;
    unsigned i = rem & 2047u;
    unsigned h = rem >> 11;

    // d = 2047 - i = 4q + m (m warp-uniform)
    unsigned d = 2047u - i;
    unsigned q = d >> 2;
    unsigned m = d & 3u;

    // float index max: 4*(q + j4 + 256) + 3 <= 4*(511+511)+3 = 4091 < 4096. OK.
    const float4* __restrict__ p =
        reinterpret_cast<const float4*>(g_rb + (size_t)(h * 4u + m) * RB_PITCH) + q;
    float4 v0 = p[j4];            // bias(i, 4*j4 .. 4*j4+3)
    float4 v1 = p[j4 + 256u];     // bias(i, 4*(j4+256) .. +3)

    // out is float4-typed: 512 float4 per (h,i) row
    size_t row = (size_t)h * SEQ_LEN + i;                    // plane-row, batch 0
    size_t off0 = row * 512 + j4;
    size_t off1 = off0 + (size_t)NUM_HEADS * SEQ_LEN * 512;  // batch 1 plane

    __stcs(&out[off0],        v0);
    __stcs(&out[off0 + 256],  v1);
    __stcs(&out[off1],        v0);
    __stcs(&out[off1 + 256],  v1);
}

extern "C" void kernel_launch(void* const* d_in, const int* in_sizes, int n_in,
                              void* d_out, int out_size) {
    // metadata order: q (unused), e1, e2
    const float* e1 = (const float*)d_in[1];
    const float* e2 = (const float*)d_in[2];
    float4* out = (float4*)d_out;

    {
        const int total = NUM_HEADS * 4 * RB_PITCH;   // 262144
        int threads = 256;
        int blocks = total / threads;                 // 1024
        build_bias_kernel<<<blocks, threads>>>(e1, e2);
    }
    {
        // threads = H * S * (S/8) = 16 * 2048 * 256 = 8,388,608
        unsigned total = NUM_HEADS * SEQ_LEN * (SEQ_LEN / 8);
        int threads = 256;
        unsigned blocks = total / threads;            // 32768
        write_out_kernel<<<blocks, threads>>>(out);
    }
}